// round 13
// baseline (speedup 1.0000x reference)
#include <cuda_runtime.h>
#include <math.h>

#define NN 50000
#define EE 800000
#define HH 64
#define GG 256
#define CC 250
#define BEPS 1e-5f
#define NSLOPE 0.2f
#define DCAP 1024

// ---------------- device scratch (static, no runtime allocation) ----------------
static __device__ __align__(128) float  g_resA[NN*HH];
static __device__ __align__(128) float  g_resB[NN*HH];
static __device__ __align__(128) float  g_xl[NN*HH];
static __device__ __align__(128) float  g_xr[NN*HH];
static __device__ __align__(128) float  g_o[NN*HH];
static __device__ int    g_counts[NN];
static __device__ int    g_rowptr[NN+1];
static __device__ int    g_cursor[NN];
static __device__ __align__(128) int4 g_edat[EE];   // (src, attr.x bits, attr.y bits, 0)
static __device__ int    g_perm[NN];
static __device__ int    g_dhist[DCAP];
static __device__ float  g_red[1280];            // 7 BN slices of (sum[64], sumsq[64])
static __device__ unsigned g_pooled[GG*HH];
static __device__ __align__(128) float  g_z[GG*256];
static __device__ float  g_pscale[256];
static __device__ float  g_pshift[256];

// ---------------- setup: zero + CSR build (by dst) ----------------
__global__ void k_zero_red() {
    int idx = blockIdx.x*blockDim.x + threadIdx.x;
    if (idx < 1280) g_red[idx] = 0.f;
}

__global__ void k_zero_csr() {
    int idx = blockIdx.x*blockDim.x + threadIdx.x;
    if (idx < NN)    g_counts[idx] = 0;
    if (idx < GG*HH) g_pooled[idx] = 0xFF800000u;   // -inf bits
    if (idx < DCAP)  g_dhist[idx] = 0;
}

__global__ void k_hist(const int* __restrict__ dst) {
    int e = blockIdx.x*blockDim.x + threadIdx.x;
    if (e < EE) atomicAdd(&g_counts[dst[e]], 1);
}

__global__ void k_scan() {
    __shared__ int sh[1024];
    int tid = threadIdx.x;
    const int CHK = (NN + 1023) / 1024;
    int b = tid*CHK; if (b > NN) b = NN;
    int e = b + CHK; if (e > NN) e = NN;
    int s = 0;
    #pragma unroll 4
    for (int i = b; i < e; i++) s += g_counts[i];
    sh[tid] = s;
    __syncthreads();
    for (int off = 1; off < 1024; off <<= 1) {
        int v = (tid >= off) ? sh[tid-off] : 0;
        __syncthreads();
        sh[tid] += v;
        __syncthreads();
    }
    int run = (tid == 0) ? 0 : sh[tid-1];
    for (int i = b; i < e; i++) {
        g_rowptr[i] = run; g_cursor[i] = run;
        run += g_counts[i];
    }
    if (tid == 0) g_rowptr[NN] = sh[1023];
}

__global__ void k_scatter(const int* __restrict__ src, const int* __restrict__ dst,
                          const float* __restrict__ eattr) {
    int e = blockIdx.x*blockDim.x + threadIdx.x;
    if (e >= EE) return;
    int d   = dst[e];
    int pos = atomicAdd(&g_cursor[d], 1);
    float2 ea = ((const float2*)eattr)[e];
    g_edat[pos] = make_int4(src[e], __float_as_int(ea.x), __float_as_int(ea.y), 0);
}

// ---------------- degree counting-sort: perm pairs nodes of equal degree ------------
__global__ void k_deghist() {
    int n = blockIdx.x*blockDim.x + threadIdx.x;
    if (n < NN) {
        int d = g_counts[n]; if (d >= DCAP) d = DCAP - 1;
        atomicAdd(&g_dhist[d], 1);
    }
}

__global__ void k_degscan() {     // exclusive scan of g_dhist (1024), then reuse as cursors
    __shared__ int sh[DCAP];
    int tid = threadIdx.x;
    sh[tid] = g_dhist[tid];
    __syncthreads();
    for (int off = 1; off < DCAP; off <<= 1) {
        int v = (tid >= off) ? sh[tid-off] : 0;
        __syncthreads();
        sh[tid] += v;
        __syncthreads();
    }
    g_dhist[tid] = (tid == 0) ? 0 : sh[tid-1];   // exclusive offsets / cursors
}

__global__ void k_degscatter() {
    int n = blockIdx.x*blockDim.x + threadIdx.x;
    if (n < NN) {
        int d = g_counts[n]; if (d >= DCAP) d = DCAP - 1;
        int pos = atomicAdd(&g_dhist[d], 1);
        g_perm[pos] = n;
    }
}

// ---------------- fused GEMM (round-6 fp32 best): BN/PReLU/residual, optional stats ---
__global__ void k_gemm(const float* __restrict__ src,
                       const float* __restrict__ red,     // null -> raw input
                       const float* __restrict__ gam, const float* __restrict__ bet,
                       const float* __restrict__ aptr,
                       const float* __restrict__ res,     // optional residual
                       float* __restrict__ hout,          // optional: store transformed h
                       const float* __restrict__ Wl, const float* __restrict__ bl,
                       const float* __restrict__ Wr, const float* __restrict__ br,
                       float* __restrict__ outL, float* __restrict__ outR, int dual,
                       float* __restrict__ statsp)        // optional: BN stats of outL
{
    __shared__ float hs[64][65];
    __shared__ float wsL[32][68];
    __shared__ float wsR[32][68];
    __shared__ float s_sc[64], s_sf[64];
    __shared__ float s_red[128];
    int row0 = blockIdx.x * 64;
    int tid  = threadIdx.x;
    float a = 0.f;
    if (red) {
        if (tid < 64) {
            float mean = red[tid] * (1.0f/(float)NN);
            float var  = red[64+tid] * (1.0f/(float)NN) - mean*mean;
            float sc   = gam[tid] * rsqrtf(var + BEPS);
            s_sc[tid] = sc;
            s_sf[tid] = bet[tid] - mean*sc;
        }
        a = *aptr;
    }
    if (statsp && tid < 128) s_red[tid] = 0.f;
    __syncthreads();

    for (int i = tid; i < 64*16; i += 256) {
        int r = i >> 4, kq = i & 15;
        int rr = row0 + r;
        float4 v = make_float4(0.f,0.f,0.f,0.f);
        if (rr < NN) {
            v = ((const float4*)src)[rr*16 + kq];
            if (red) {
                int k = kq*4;
                float4 rs = res ? ((const float4*)res)[rr*16 + kq]
                                : make_float4(0.f,0.f,0.f,0.f);
                float t;
                t = s_sc[k+0]*v.x + s_sf[k+0] + rs.x; v.x = fmaxf(t, a*t);
                t = s_sc[k+1]*v.y + s_sf[k+1] + rs.y; v.y = fmaxf(t, a*t);
                t = s_sc[k+2]*v.z + s_sf[k+2] + rs.z; v.z = fmaxf(t, a*t);
                t = s_sc[k+3]*v.w + s_sf[k+3] + rs.w; v.w = fmaxf(t, a*t);
            }
            if (hout) ((float4*)hout)[rr*16 + kq] = v;
        }
        hs[kq*4+0][r] = v.x;
        hs[kq*4+1][r] = v.y;
        hs[kq*4+2][r] = v.z;
        hs[kq*4+3][r] = v.w;
    }

    int c0 = tid & 15;
    int r0 = (tid >> 4) * 4;
    float acc[4][8];
    #pragma unroll
    for (int i = 0; i < 4; i++)
        #pragma unroll
        for (int j = 0; j < 8; j++) acc[i][j] = 0.f;

    for (int ph = 0; ph < 2; ph++) {
        __syncthreads();
        for (int i = tid; i < 32*64; i += 256) {
            int kk = i & 31, c = i >> 5;
            int k = ph*32 + kk;
            wsL[kk][c] = Wl[c*64 + k];
            if (dual) wsR[kk][c] = Wr[c*64 + k];
        }
        __syncthreads();
        #pragma unroll 8
        for (int kk = 0; kk < 32; kk++) {
            float rh[4];
            #pragma unroll
            for (int i = 0; i < 4; i++) rh[i] = hs[ph*32 + kk][r0 + i];
            float4 wl4 = *(const float4*)&wsL[kk][c0*4];
            float wv[8];
            wv[0]=wl4.x; wv[1]=wl4.y; wv[2]=wl4.z; wv[3]=wl4.w;
            if (dual) {
                float4 wr4 = *(const float4*)&wsR[kk][c0*4];
                wv[4]=wr4.x; wv[5]=wr4.y; wv[6]=wr4.z; wv[7]=wr4.w;
                #pragma unroll
                for (int i = 0; i < 4; i++)
                    #pragma unroll
                    for (int j = 0; j < 8; j++)
                        acc[i][j] = fmaf(rh[i], wv[j], acc[i][j]);
            } else {
                #pragma unroll
                for (int i = 0; i < 4; i++)
                    #pragma unroll
                    for (int j = 0; j < 4; j++)
                        acc[i][j] = fmaf(rh[i], wv[j], acc[i][j]);
            }
        }
    }

    float4 bl4 = *(const float4*)&bl[c0*4];
    float4 br4 = dual ? *(const float4*)&br[c0*4] : make_float4(0,0,0,0);
    float a_s[4] = {0.f,0.f,0.f,0.f};
    float a_q[4] = {0.f,0.f,0.f,0.f};
    for (int i = 0; i < 4; i++) {
        int rr = row0 + r0 + i;
        if (rr >= NN) continue;
        float4 vL = make_float4(acc[i][0]+bl4.x, acc[i][1]+bl4.y,
                                acc[i][2]+bl4.z, acc[i][3]+bl4.w);
        ((float4*)outL)[rr*16 + c0] = vL;
        if (statsp) {
            a_s[0]+=vL.x; a_s[1]+=vL.y; a_s[2]+=vL.z; a_s[3]+=vL.w;
            a_q[0]+=vL.x*vL.x; a_q[1]+=vL.y*vL.y; a_q[2]+=vL.z*vL.z; a_q[3]+=vL.w*vL.w;
        }
        if (dual) {
            float4 vR = make_float4(acc[i][4]+br4.x, acc[i][5]+br4.y,
                                    acc[i][6]+br4.z, acc[i][7]+br4.w);
            ((float4*)outR)[rr*16 + c0] = vR;
        }
    }
    if (statsp) {
        #pragma unroll
        for (int j = 0; j < 4; j++) {
            int c = c0*4 + j;
            atomicAdd(&s_red[c],      a_s[j]);
            atomicAdd(&s_red[64 + c], a_q[j]);
        }
        __syncthreads();
        if (tid < 128) atomicAdd(&statsp[tid], s_red[tid]);
    }
}

// ---------------- fused GATv2 edge kernel: degree-matched 2 nodes/warp --------------
// identical round-12 loop body; node IDs come from the degree-sorted permutation so
// both warp halves run (nearly) the same number of 8-edge batches.
__global__ void k_edge(const float* __restrict__ We, const float* __restrict__ att,
                       float* __restrict__ redp) {
    __shared__ float s_acc[128];
    int tid  = threadIdx.x;
    int lane = tid & 31;
    int lh   = lane & 15;                       // channel group within node
    int node = g_perm[blockIdx.x*16 + ((tid >> 5) << 1) + (lane >> 4)];
    if (tid < 128) s_acc[tid] = 0.f;
    __syncthreads();

    int beg = g_rowptr[node], cnt = g_rowptr[node+1] - beg;

    float4 wA   = ((const float4*)We)[lh*2];
    float4 wB   = ((const float4*)We)[lh*2 + 1];
    float4 at4  = ((const float4*)att)[lh];
    float4 xr4  = ((const float4*)g_xr)[node*16 + lh];
    const float4* xl4 = (const float4*)g_xl;

    float M = -INFINITY, S = 0.f;
    float4 acc = make_float4(0.f,0.f,0.f,0.f);

    int myits = (cnt + 7) >> 3;
    int oits  = __shfl_xor_sync(0xffffffffu, myits, 16);
    int loops = max(myits, oits);

    for (int it = 0; it < loops; it++) {
        int i0 = it*8;
        float  l[8];
        float4 xx[8];
        #pragma unroll
        for (int j = 0; j < 8; j++) {
            int i = i0 + j;
            bool v = (i < cnt);
            int e  = v ? (beg + i) : 0;
            int4 ed = g_edat[e];                 // one LDG.128: src + attr
            int s   = ed.x;
            float eax = __int_as_float(ed.y);
            float eay = __int_as_float(ed.z);
            float4 x  = xl4[s*16 + lh];
            xx[j] = x;
            float m0 = x.x + xr4.x + wA.x*eax + wA.y*eay;
            float m1 = x.y + xr4.y + wA.z*eax + wA.w*eay;
            float m2 = x.z + xr4.z + wB.x*eax + wB.y*eay;
            float m3 = x.w + xr4.w + wB.z*eax + wB.w*eay;
            m0 = fmaxf(m0, NSLOPE*m0);
            m1 = fmaxf(m1, NSLOPE*m1);
            m2 = fmaxf(m2, NSLOPE*m2);
            m3 = fmaxf(m3, NSLOPE*m3);
            l[j] = at4.x*m0 + at4.y*m1 + at4.z*m2 + at4.w*m3;
        }
        #pragma unroll
        for (int off = 8; off > 0; off >>= 1) {
            #pragma unroll
            for (int j = 0; j < 8; j++)
                l[j] += __shfl_xor_sync(0xffffffffu, l[j], off);
        }
        if (i0 < cnt) {
            #pragma unroll
            for (int j = 0; j < 8; j++)
                if (i0 + j >= cnt) l[j] = -INFINITY;
            float b01 = fmaxf(l[0], l[1]), b23 = fmaxf(l[2], l[3]);
            float b45 = fmaxf(l[4], l[5]), b67 = fmaxf(l[6], l[7]);
            float bmax = fmaxf(fmaxf(b01, b23), fmaxf(b45, b67));
            float newM = fmaxf(M, bmax);
            float scl  = __expf(M - newM);   // first batch: exp(-inf)=0
            S *= scl;
            acc.x *= scl; acc.y *= scl; acc.z *= scl; acc.w *= scl;
            M = newM;
            #pragma unroll
            for (int j = 0; j < 8; j++) {
                float wt = __expf(l[j] - M); // invalid: exp(-inf)=0
                S += wt;
                acc.x = fmaf(wt, xx[j].x, acc.x);
                acc.y = fmaf(wt, xx[j].y, acc.y);
                acc.z = fmaf(wt, xx[j].z, acc.z);
                acc.w = fmaf(wt, xx[j].w, acc.w);
            }
        }
    }

    float4 out = make_float4(0.f,0.f,0.f,0.f);
    if (cnt > 0) {
        float inv = 1.f / S;
        out = make_float4(acc.x*inv, acc.y*inv, acc.z*inv, acc.w*inv);
    }
    ((float4*)g_o)[node*16 + lh] = out;

    int ch = lh*4;
    atomicAdd(&s_acc[ch+0], out.x);  atomicAdd(&s_acc[ch+1], out.y);
    atomicAdd(&s_acc[ch+2], out.z);  atomicAdd(&s_acc[ch+3], out.w);
    atomicAdd(&s_acc[64+ch+0], out.x*out.x);  atomicAdd(&s_acc[64+ch+1], out.y*out.y);
    atomicAdd(&s_acc[64+ch+2], out.z*out.z);  atomicAdd(&s_acc[64+ch+3], out.w*out.w);
    __syncthreads();
    if (tid < 128) atomicAdd(&redp[tid], s_acc[tid]);
}

// ---------------- final: BN + residual + PReLU + segment-max pool (float4) ----------
__global__ void k_final(const float* __restrict__ red,
                        const float* __restrict__ gam, const float* __restrict__ bet,
                        const float* __restrict__ aptr, const float* __restrict__ res,
                        const int* __restrict__ batch) {
    int idx = blockIdx.x*blockDim.x + threadIdx.x;
    if (idx >= NN*16) return;
    int n = idx >> 4, q = idx & 15;
    float a = *aptr;
    float4 o = ((const float4*)g_o)[idx];
    float4 r = ((const float4*)res)[idx];
    int g = batch[n];
    float hv[4]; float oi[4] = {o.x,o.y,o.z,o.w}; float ri[4] = {r.x,r.y,r.z,r.w};
    #pragma unroll
    for (int i = 0; i < 4; i++) {
        int c = q*4 + i;
        float mean = red[c] * (1.0f/(float)NN);
        float var  = red[64 + c] * (1.0f/(float)NN) - mean*mean;
        float sc   = gam[c] * rsqrtf(var + BEPS);
        float sf   = bet[c] - mean*sc;
        float t = sc*oi[i] + sf + ri[i];
        hv[i] = (t >= 0.f) ? t : a*t;
    }
    #pragma unroll
    for (int i = 0; i < 4; i++) {
        int c = q*4 + i;
        unsigned* addr = &g_pooled[g*64 + c];
        if (hv[i] >= 0.f) atomicMax((int*)addr, __float_as_int(hv[i]));
        else              atomicMin(addr, __float_as_uint(hv[i]));
    }
}

// ---------------- classifier head: warp-per-output coalesced dots ----------------
__global__ void k_postg1(const float* __restrict__ W1) {
    __shared__ float row[64];
    int g = blockIdx.x;
    int w = threadIdx.x >> 5, lane = threadIdx.x & 31;
    if (threadIdx.x < 64) row[threadIdx.x] = __uint_as_float(g_pooled[g*64 + threadIdx.x]);
    __syncthreads();
    float r0 = row[lane], r1 = row[32 + lane];
    for (int j = w; j < 256; j += 8) {
        float p = r0 * W1[j*64 + lane] + r1 * W1[j*64 + 32 + lane];
        #pragma unroll
        for (int off = 16; off > 0; off >>= 1)
            p += __shfl_xor_sync(0xffffffffu, p, off);
        if (lane == 0) g_z[g*256 + j] = p;
    }
}

__global__ void k_poststats(const float* __restrict__ pg, const float* __restrict__ pb) {
    int c = threadIdx.x;
    float s = 0.f, q = 0.f;
    for (int r = 0; r < GG; r++) { float v = g_z[r*256 + c]; s += v; q += v*v; }
    float mean = s * (1.0f/(float)GG);
    float var  = q * (1.0f/(float)GG) - mean*mean;
    float sc   = pg[c] * rsqrtf(var + BEPS);
    g_pscale[c] = sc;
    g_pshift[c] = pb[c] - mean*sc;
}

__global__ void k_postg2(const float* __restrict__ aptr, const float* __restrict__ W2,
                         const float* __restrict__ b2, float* __restrict__ out) {
    __shared__ float row[256];
    int g = blockIdx.x;
    int tid = threadIdx.x;
    int w = tid >> 5, lane = tid & 31;
    float a = *aptr;
    float v = g_z[g*256 + tid];
    v = g_pscale[tid]*v + g_pshift[tid];
    row[tid] = (v >= 0.f) ? v : a*v;
    __syncthreads();
    float rv[8];
    #pragma unroll
    for (int i = 0; i < 8; i++) rv[i] = row[lane + 32*i];
    for (int c = w; c < CC; c += 8) {
        float p = 0.f;
        #pragma unroll
        for (int i = 0; i < 8; i++)
            p = fmaf(rv[i], W2[c*256 + lane + 32*i], p);
        #pragma unroll
        for (int off = 16; off > 0; off >>= 1)
            p += __shfl_xor_sync(0xffffffffu, p, off);
        if (lane == 0) out[g*CC + c] = p + b2[c];
    }
}

// ---------------- launch ----------------
extern "C" void kernel_launch(void* const* d_in, const int* in_sizes, int n_in,
                              void* d_out, int out_size) {
    const float* x         = (const float*)d_in[0];
    const int*   ei        = (const int*)  d_in[1];
    const float* eattr     = (const float*)d_in[2];
    const int*   batch     = (const int*)  d_in[3];
    const float* pre_W     = (const float*)d_in[4];
    const float* pre_b     = (const float*)d_in[5];
    const float* pre_g     = (const float*)d_in[6];
    const float* pre_beta  = (const float*)d_in[7];
    const float* pre_a     = (const float*)d_in[8];
    const float* blk_Wl    = (const float*)d_in[9];
    const float* blk_bl    = (const float*)d_in[10];
    const float* blk_Wr    = (const float*)d_in[11];
    const float* blk_br    = (const float*)d_in[12];
    const float* blk_We    = (const float*)d_in[13];
    const float* blk_att   = (const float*)d_in[14];
    // d_in[15] = blk_cb : exactly cancelled by the following BatchNorm
    const float* blk_bng   = (const float*)d_in[16];
    const float* blk_bnb   = (const float*)d_in[17];
    const float* blk_pa    = (const float*)d_in[18];
    const float* post_W1   = (const float*)d_in[19];
    // d_in[20] = post_b1 : cancelled by post BN
    const float* post_g    = (const float*)d_in[21];
    const float* post_beta = (const float*)d_in[22];
    const float* post_a    = (const float*)d_in[23];
    const float* post_W2   = (const float*)d_in[24];
    const float* post_b2   = (const float*)d_in[25];

    const int* srcI = ei;
    const int* dstI = ei + EE;

    float *pRA, *pRB, *pXL, *pXR, *pO, *pRED;
    cudaGetSymbolAddress((void**)&pRA,  g_resA);
    cudaGetSymbolAddress((void**)&pRB,  g_resB);
    cudaGetSymbolAddress((void**)&pXL,  g_xl);
    cudaGetSymbolAddress((void**)&pXR,  g_xr);
    cudaGetSymbolAddress((void**)&pO,   g_o);
    cudaGetSymbolAddress((void**)&pRED, g_red);

    const int GEMM_GRID  = (NN + 63) / 64;
    const int EDGE_GRID  = NN / 16;

    // side stream: CSR build + degree sort, overlapped with pre+L0 GEMMs
    cudaStream_t s2;
    cudaStreamCreateWithFlags(&s2, cudaStreamNonBlocking);
    cudaEvent_t evFork, evJoin;
    cudaEventCreateWithFlags(&evFork, cudaEventDisableTiming);
    cudaEventCreateWithFlags(&evJoin, cudaEventDisableTiming);

    cudaEventRecord(evFork, 0);
    cudaStreamWaitEvent(s2, evFork, 0);
    k_zero_csr  <<<200, 256, 0, s2>>>();
    k_hist      <<<(EE + 255)/256, 256, 0, s2>>>(dstI);
    k_scan      <<<1, 1024, 0, s2>>>();
    k_scatter   <<<(EE + 255)/256, 256, 0, s2>>>(srcI, dstI, eattr);
    k_deghist   <<<(NN + 255)/256, 256, 0, s2>>>();
    k_degscan   <<<1, DCAP, 0, s2>>>();
    k_degscatter<<<(NN + 255)/256, 256, 0, s2>>>();
    cudaEventRecord(evJoin, s2);

    // main stream: BN-slice zero, then pre-GEMM (stats -> red slice 0)
    k_zero_red<<<5, 256>>>();
    k_gemm<<<GEMM_GRID, 256>>>(x, nullptr, nullptr, nullptr, nullptr, nullptr, nullptr,
                               pre_W, pre_b, pre_W, pre_b,
                               pO, nullptr, 0, pRED);

    for (int L = 0; L < 6; L++) {
        const float* Wl = blk_Wl  + L*HH*HH;
        const float* bl = blk_bl  + L*HH;
        const float* Wr = blk_Wr  + L*HH*HH;
        const float* br = blk_br  + L*HH;
        const float* We = blk_We  + L*HH*2;
        const float* at = blk_att + L*HH;

        const float* ared, *agam, *abet, *aa, *ares;
        if (L == 0) {
            ared = pRED; agam = pre_g; abet = pre_beta; aa = pre_a; ares = nullptr;
        } else {
            ared = pRED + L*128;
            agam = blk_bng + (L-1)*HH;
            abet = blk_bnb + (L-1)*HH;
            aa   = blk_pa  + (L-1);
            ares = ((L & 1) == 0) ? ((L == 2) ? pRA : pRB) : nullptr; // prev conv2 residual
        }
        float* hout = ((L & 1) == 0) ? ((L == 0 || L == 4) ? pRA : pRB) : nullptr;

        k_gemm<<<GEMM_GRID, 256>>>(pO, ared, agam, abet, aa, ares, hout,
                                   Wl, bl, Wr, br, pXL, pXR, 1, nullptr);
        if (L == 0) cudaStreamWaitEvent(0, evJoin, 0);   // CSR+perm ready before edges
        k_edge<<<EDGE_GRID, 256>>>(We, at, pRED + (L+1)*128);
    }

    // final apply (block2 conv2) + pooling; residual = resA (written at L=4)
    k_final<<<(NN*16 + 255)/256, 256>>>(pRED + 6*128, blk_bng + 5*HH, blk_bnb + 5*HH,
                                        blk_pa + 5, pRA, batch);

    k_postg1   <<<GG, 256>>>(post_W1);
    k_poststats<<<1, 256>>>(post_g, post_beta);
    k_postg2   <<<GG, 256>>>(post_a, post_W2, post_b2, (float*)d_out);

    cudaEventDestroy(evFork);
    cudaEventDestroy(evJoin);
    cudaStreamDestroy(s2);
}

// round 14
// speedup vs baseline: 1.0563x; 1.0563x over previous
#include <cuda_runtime.h>
#include <math.h>

#define NN 50000
#define EE 800000
#define HH 64
#define GG 256
#define CC 250
#define BEPS 1e-5f
#define NSLOPE 0.2f

// ---------------- device scratch (static, no runtime allocation) ----------------
static __device__ __align__(128) float  g_resA[NN*HH];
static __device__ __align__(128) float  g_resB[NN*HH];
static __device__ __align__(128) float  g_xl[NN*HH];
static __device__ __align__(128) float  g_xr[NN*HH];
static __device__ __align__(128) float  g_o[NN*HH];
static __device__ int    g_counts[NN];
static __device__ int    g_rowptr[NN+1];
static __device__ int    g_cursor[NN];
static __device__ __align__(128) int4 g_edat[EE];   // (src, attr.x bits, attr.y bits, 0)
static __device__ float  g_red[1280];            // 7 BN slices of (sum[64], sumsq[64])
static __device__ unsigned g_pooled[GG*HH];
static __device__ __align__(128) float  g_z[GG*256];
static __device__ float  g_pscale[256];
static __device__ float  g_pshift[256];

// ---------------- setup: zero + CSR build (by dst) ----------------
__global__ void k_zero_red() {
    int idx = blockIdx.x*blockDim.x + threadIdx.x;
    if (idx < 1280) g_red[idx] = 0.f;
}

__global__ void k_zero_csr() {
    int idx = blockIdx.x*blockDim.x + threadIdx.x;
    if (idx < NN)    g_counts[idx] = 0;
    if (idx < GG*HH) g_pooled[idx] = 0xFF800000u;   // -inf bits
}

__global__ void k_hist(const int* __restrict__ dst) {
    int e = blockIdx.x*blockDim.x + threadIdx.x;
    if (e < EE) atomicAdd(&g_counts[dst[e]], 1);
}

__global__ void k_scan() {
    __shared__ int sh[1024];
    int tid = threadIdx.x;
    const int CHK = (NN + 1023) / 1024;
    int b = tid*CHK; if (b > NN) b = NN;
    int e = b + CHK; if (e > NN) e = NN;
    int s = 0;
    #pragma unroll 4
    for (int i = b; i < e; i++) s += g_counts[i];
    sh[tid] = s;
    __syncthreads();
    for (int off = 1; off < 1024; off <<= 1) {
        int v = (tid >= off) ? sh[tid-off] : 0;
        __syncthreads();
        sh[tid] += v;
        __syncthreads();
    }
    int run = (tid == 0) ? 0 : sh[tid-1];
    for (int i = b; i < e; i++) {
        g_rowptr[i] = run; g_cursor[i] = run;
        run += g_counts[i];
    }
    if (tid == 0) g_rowptr[NN] = sh[1023];
}

__global__ void k_scatter(const int* __restrict__ src, const int* __restrict__ dst,
                          const float* __restrict__ eattr) {
    int e = blockIdx.x*blockDim.x + threadIdx.x;
    if (e >= EE) return;
    int d   = dst[e];
    int pos = atomicAdd(&g_cursor[d], 1);
    float2 ea = ((const float2*)eattr)[e];
    g_edat[pos] = make_int4(src[e], __float_as_int(ea.x), __float_as_int(ea.y), 0);
}

// ---------------- fused GEMM (round-6 fp32 best): BN/PReLU/residual, optional stats ---
__global__ void k_gemm(const float* __restrict__ src,
                       const float* __restrict__ red,     // null -> raw input
                       const float* __restrict__ gam, const float* __restrict__ bet,
                       const float* __restrict__ aptr,
                       const float* __restrict__ res,     // optional residual
                       float* __restrict__ hout,          // optional: store transformed h
                       const float* __restrict__ Wl, const float* __restrict__ bl,
                       const float* __restrict__ Wr, const float* __restrict__ br,
                       float* __restrict__ outL, float* __restrict__ outR, int dual,
                       float* __restrict__ statsp)        // optional: BN stats of outL
{
    __shared__ float hs[64][65];
    __shared__ float wsL[32][68];
    __shared__ float wsR[32][68];
    __shared__ float s_sc[64], s_sf[64];
    __shared__ float s_red[128];
    int row0 = blockIdx.x * 64;
    int tid  = threadIdx.x;
    float a = 0.f;
    if (red) {
        if (tid < 64) {
            float mean = red[tid] * (1.0f/(float)NN);
            float var  = red[64+tid] * (1.0f/(float)NN) - mean*mean;
            float sc   = gam[tid] * rsqrtf(var + BEPS);
            s_sc[tid] = sc;
            s_sf[tid] = bet[tid] - mean*sc;
        }
        a = *aptr;
    }
    if (statsp && tid < 128) s_red[tid] = 0.f;
    __syncthreads();

    for (int i = tid; i < 64*16; i += 256) {
        int r = i >> 4, kq = i & 15;
        int rr = row0 + r;
        float4 v = make_float4(0.f,0.f,0.f,0.f);
        if (rr < NN) {
            v = ((const float4*)src)[rr*16 + kq];
            if (red) {
                int k = kq*4;
                float4 rs = res ? ((const float4*)res)[rr*16 + kq]
                                : make_float4(0.f,0.f,0.f,0.f);
                float t;
                t = s_sc[k+0]*v.x + s_sf[k+0] + rs.x; v.x = fmaxf(t, a*t);
                t = s_sc[k+1]*v.y + s_sf[k+1] + rs.y; v.y = fmaxf(t, a*t);
                t = s_sc[k+2]*v.z + s_sf[k+2] + rs.z; v.z = fmaxf(t, a*t);
                t = s_sc[k+3]*v.w + s_sf[k+3] + rs.w; v.w = fmaxf(t, a*t);
            }
            if (hout) ((float4*)hout)[rr*16 + kq] = v;
        }
        hs[kq*4+0][r] = v.x;
        hs[kq*4+1][r] = v.y;
        hs[kq*4+2][r] = v.z;
        hs[kq*4+3][r] = v.w;
    }

    int c0 = tid & 15;
    int r0 = (tid >> 4) * 4;
    float acc[4][8];
    #pragma unroll
    for (int i = 0; i < 4; i++)
        #pragma unroll
        for (int j = 0; j < 8; j++) acc[i][j] = 0.f;

    for (int ph = 0; ph < 2; ph++) {
        __syncthreads();
        for (int i = tid; i < 32*64; i += 256) {
            int kk = i & 31, c = i >> 5;
            int k = ph*32 + kk;
            wsL[kk][c] = Wl[c*64 + k];
            if (dual) wsR[kk][c] = Wr[c*64 + k];
        }
        __syncthreads();
        #pragma unroll 8
        for (int kk = 0; kk < 32; kk++) {
            float rh[4];
            #pragma unroll
            for (int i = 0; i < 4; i++) rh[i] = hs[ph*32 + kk][r0 + i];
            float4 wl4 = *(const float4*)&wsL[kk][c0*4];
            float wv[8];
            wv[0]=wl4.x; wv[1]=wl4.y; wv[2]=wl4.z; wv[3]=wl4.w;
            if (dual) {
                float4 wr4 = *(const float4*)&wsR[kk][c0*4];
                wv[4]=wr4.x; wv[5]=wr4.y; wv[6]=wr4.z; wv[7]=wr4.w;
                #pragma unroll
                for (int i = 0; i < 4; i++)
                    #pragma unroll
                    for (int j = 0; j < 8; j++)
                        acc[i][j] = fmaf(rh[i], wv[j], acc[i][j]);
            } else {
                #pragma unroll
                for (int i = 0; i < 4; i++)
                    #pragma unroll
                    for (int j = 0; j < 4; j++)
                        acc[i][j] = fmaf(rh[i], wv[j], acc[i][j]);
            }
        }
    }

    float4 bl4 = *(const float4*)&bl[c0*4];
    float4 br4 = dual ? *(const float4*)&br[c0*4] : make_float4(0,0,0,0);
    float a_s[4] = {0.f,0.f,0.f,0.f};
    float a_q[4] = {0.f,0.f,0.f,0.f};
    for (int i = 0; i < 4; i++) {
        int rr = row0 + r0 + i;
        if (rr >= NN) continue;
        float4 vL = make_float4(acc[i][0]+bl4.x, acc[i][1]+bl4.y,
                                acc[i][2]+bl4.z, acc[i][3]+bl4.w);
        ((float4*)outL)[rr*16 + c0] = vL;
        if (statsp) {
            a_s[0]+=vL.x; a_s[1]+=vL.y; a_s[2]+=vL.z; a_s[3]+=vL.w;
            a_q[0]+=vL.x*vL.x; a_q[1]+=vL.y*vL.y; a_q[2]+=vL.z*vL.z; a_q[3]+=vL.w*vL.w;
        }
        if (dual) {
            float4 vR = make_float4(acc[i][4]+br4.x, acc[i][5]+br4.y,
                                    acc[i][6]+br4.z, acc[i][7]+br4.w);
            ((float4*)outR)[rr*16 + c0] = vR;
        }
    }
    if (statsp) {
        #pragma unroll
        for (int j = 0; j < 4; j++) {
            int c = c0*4 + j;
            atomicAdd(&s_red[c],      a_s[j]);
            atomicAdd(&s_red[64 + c], a_q[j]);
        }
        __syncthreads();
        if (tid < 128) atomicAdd(&statsp[tid], s_red[tid]);
    }
}

// ---------------- fused GATv2 edge kernel (round-12 best loop, lighter stats) -------
// 2 nodes/warp, 16 lanes/node, float4/lane, 8-edge register batches, packed edge data.
// BN-stats epilogue pre-reduces the warp's two nodes via shfl before smem atomics.
__global__ void k_edge(const float* __restrict__ We, const float* __restrict__ att,
                       float* __restrict__ redp) {
    __shared__ float s_acc[128];
    int tid  = threadIdx.x;
    int lane = tid & 31;
    int lh   = lane & 15;                       // channel group within node
    int node = blockIdx.x*16 + ((tid >> 5) << 1) + (lane >> 4);
    if (tid < 128) s_acc[tid] = 0.f;
    __syncthreads();

    int beg = g_rowptr[node], cnt = g_rowptr[node+1] - beg;

    float4 wA   = ((const float4*)We)[lh*2];
    float4 wB   = ((const float4*)We)[lh*2 + 1];
    float4 at4  = ((const float4*)att)[lh];
    float4 xr4  = ((const float4*)g_xr)[node*16 + lh];
    const float4* xl4 = (const float4*)g_xl;

    float M = -INFINITY, S = 0.f;
    float4 acc = make_float4(0.f,0.f,0.f,0.f);

    int myits = (cnt + 7) >> 3;
    int oits  = __shfl_xor_sync(0xffffffffu, myits, 16);
    int loops = max(myits, oits);

    for (int it = 0; it < loops; it++) {
        int i0 = it*8;
        float  l[8];
        float4 xx[8];
        #pragma unroll
        for (int j = 0; j < 8; j++) {
            int i = i0 + j;
            bool v = (i < cnt);
            int e  = v ? (beg + i) : 0;
            int4 ed = g_edat[e];                 // one LDG.128: src + attr
            int s   = ed.x;
            float eax = __int_as_float(ed.y);
            float eay = __int_as_float(ed.z);
            float4 x  = xl4[s*16 + lh];
            xx[j] = x;
            float m0 = x.x + xr4.x + wA.x*eax + wA.y*eay;
            float m1 = x.y + xr4.y + wA.z*eax + wA.w*eay;
            float m2 = x.z + xr4.z + wB.x*eax + wB.y*eay;
            float m3 = x.w + xr4.w + wB.z*eax + wB.w*eay;
            m0 = fmaxf(m0, NSLOPE*m0);
            m1 = fmaxf(m1, NSLOPE*m1);
            m2 = fmaxf(m2, NSLOPE*m2);
            m3 = fmaxf(m3, NSLOPE*m3);
            l[j] = at4.x*m0 + at4.y*m1 + at4.z*m2 + at4.w*m3;
        }
        #pragma unroll
        for (int off = 8; off > 0; off >>= 1) {
            #pragma unroll
            for (int j = 0; j < 8; j++)
                l[j] += __shfl_xor_sync(0xffffffffu, l[j], off);
        }
        if (i0 < cnt) {
            #pragma unroll
            for (int j = 0; j < 8; j++)
                if (i0 + j >= cnt) l[j] = -INFINITY;
            float b01 = fmaxf(l[0], l[1]), b23 = fmaxf(l[2], l[3]);
            float b45 = fmaxf(l[4], l[5]), b67 = fmaxf(l[6], l[7]);
            float bmax = fmaxf(fmaxf(b01, b23), fmaxf(b45, b67));
            float newM = fmaxf(M, bmax);
            float scl  = __expf(M - newM);   // first batch: exp(-inf)=0
            S *= scl;
            acc.x *= scl; acc.y *= scl; acc.z *= scl; acc.w *= scl;
            M = newM;
            #pragma unroll
            for (int j = 0; j < 8; j++) {
                float wt = __expf(l[j] - M); // invalid: exp(-inf)=0
                S += wt;
                acc.x = fmaf(wt, xx[j].x, acc.x);
                acc.y = fmaf(wt, xx[j].y, acc.y);
                acc.z = fmaf(wt, xx[j].z, acc.z);
                acc.w = fmaf(wt, xx[j].w, acc.w);
            }
        }
    }

    float4 out = make_float4(0.f,0.f,0.f,0.f);
    if (cnt > 0) {
        float inv = 1.f / S;
        out = make_float4(acc.x*inv, acc.y*inv, acc.z*inv, acc.w*inv);
    }
    ((float4*)g_o)[node*16 + lh] = out;

    // BN stats: pre-reduce the warp's two nodes (same channels at lane, lane^16)
    float s0 = out.x, s1 = out.y, s2 = out.z, s3 = out.w;
    float q0 = out.x*out.x, q1 = out.y*out.y, q2 = out.z*out.z, q3 = out.w*out.w;
    s0 += __shfl_xor_sync(0xffffffffu, s0, 16);
    s1 += __shfl_xor_sync(0xffffffffu, s1, 16);
    s2 += __shfl_xor_sync(0xffffffffu, s2, 16);
    s3 += __shfl_xor_sync(0xffffffffu, s3, 16);
    q0 += __shfl_xor_sync(0xffffffffu, q0, 16);
    q1 += __shfl_xor_sync(0xffffffffu, q1, 16);
    q2 += __shfl_xor_sync(0xffffffffu, q2, 16);
    q3 += __shfl_xor_sync(0xffffffffu, q3, 16);
    if (lane < 16) {
        int ch = lh*4;
        atomicAdd(&s_acc[ch+0], s0);  atomicAdd(&s_acc[ch+1], s1);
        atomicAdd(&s_acc[ch+2], s2);  atomicAdd(&s_acc[ch+3], s3);
        atomicAdd(&s_acc[64+ch+0], q0);  atomicAdd(&s_acc[64+ch+1], q1);
        atomicAdd(&s_acc[64+ch+2], q2);  atomicAdd(&s_acc[64+ch+3], q3);
    }
    __syncthreads();
    if (tid < 128) atomicAdd(&redp[tid], s_acc[tid]);
}

// ---------------- final: BN + residual + PReLU + segment-max pool (float4) ----------
__global__ void k_final(const float* __restrict__ red,
                        const float* __restrict__ gam, const float* __restrict__ bet,
                        const float* __restrict__ aptr, const float* __restrict__ res,
                        const int* __restrict__ batch) {
    int idx = blockIdx.x*blockDim.x + threadIdx.x;
    if (idx >= NN*16) return;
    int n = idx >> 4, q = idx & 15;
    float a = *aptr;
    float4 o = ((const float4*)g_o)[idx];
    float4 r = ((const float4*)res)[idx];
    int g = batch[n];
    float hv[4]; float oi[4] = {o.x,o.y,o.z,o.w}; float ri[4] = {r.x,r.y,r.z,r.w};
    #pragma unroll
    for (int i = 0; i < 4; i++) {
        int c = q*4 + i;
        float mean = red[c] * (1.0f/(float)NN);
        float var  = red[64 + c] * (1.0f/(float)NN) - mean*mean;
        float sc   = gam[c] * rsqrtf(var + BEPS);
        float sf   = bet[c] - mean*sc;
        float t = sc*oi[i] + sf + ri[i];
        hv[i] = (t >= 0.f) ? t : a*t;
    }
    #pragma unroll
    for (int i = 0; i < 4; i++) {
        int c = q*4 + i;
        unsigned* addr = &g_pooled[g*64 + c];
        if (hv[i] >= 0.f) atomicMax((int*)addr, __float_as_int(hv[i]));
        else              atomicMin(addr, __float_as_uint(hv[i]));
    }
}

// ---------------- classifier head: warp-per-output coalesced dots ----------------
__global__ void k_postg1(const float* __restrict__ W1) {
    __shared__ float row[64];
    int g = blockIdx.x;
    int w = threadIdx.x >> 5, lane = threadIdx.x & 31;
    if (threadIdx.x < 64) row[threadIdx.x] = __uint_as_float(g_pooled[g*64 + threadIdx.x]);
    __syncthreads();
    float r0 = row[lane], r1 = row[32 + lane];
    for (int j = w; j < 256; j += 8) {
        float p = r0 * W1[j*64 + lane] + r1 * W1[j*64 + 32 + lane];
        #pragma unroll
        for (int off = 16; off > 0; off >>= 1)
            p += __shfl_xor_sync(0xffffffffu, p, off);
        if (lane == 0) g_z[g*256 + j] = p;
    }
}

__global__ void k_poststats(const float* __restrict__ pg, const float* __restrict__ pb) {
    int c = threadIdx.x;
    float s = 0.f, q = 0.f;
    for (int r = 0; r < GG; r++) { float v = g_z[r*256 + c]; s += v; q += v*v; }
    float mean = s * (1.0f/(float)GG);
    float var  = q * (1.0f/(float)GG) - mean*mean;
    float sc   = pg[c] * rsqrtf(var + BEPS);
    g_pscale[c] = sc;
    g_pshift[c] = pb[c] - mean*sc;
}

__global__ void k_postg2(const float* __restrict__ aptr, const float* __restrict__ W2,
                         const float* __restrict__ b2, float* __restrict__ out) {
    __shared__ float row[256];
    int g = blockIdx.x;
    int tid = threadIdx.x;
    int w = tid >> 5, lane = tid & 31;
    float a = *aptr;
    float v = g_z[g*256 + tid];
    v = g_pscale[tid]*v + g_pshift[tid];
    row[tid] = (v >= 0.f) ? v : a*v;
    __syncthreads();
    float rv[8];
    #pragma unroll
    for (int i = 0; i < 8; i++) rv[i] = row[lane + 32*i];
    for (int c = w; c < CC; c += 8) {
        float p = 0.f;
        #pragma unroll
        for (int i = 0; i < 8; i++)
            p = fmaf(rv[i], W2[c*256 + lane + 32*i], p);
        #pragma unroll
        for (int off = 16; off > 0; off >>= 1)
            p += __shfl_xor_sync(0xffffffffu, p, off);
        if (lane == 0) out[g*CC + c] = p + b2[c];
    }
}

// ---------------- launch ----------------
extern "C" void kernel_launch(void* const* d_in, const int* in_sizes, int n_in,
                              void* d_out, int out_size) {
    const float* x         = (const float*)d_in[0];
    const int*   ei        = (const int*)  d_in[1];
    const float* eattr     = (const float*)d_in[2];
    const int*   batch     = (const int*)  d_in[3];
    const float* pre_W     = (const float*)d_in[4];
    const float* pre_b     = (const float*)d_in[5];
    const float* pre_g     = (const float*)d_in[6];
    const float* pre_beta  = (const float*)d_in[7];
    const float* pre_a     = (const float*)d_in[8];
    const float* blk_Wl    = (const float*)d_in[9];
    const float* blk_bl    = (const float*)d_in[10];
    const float* blk_Wr    = (const float*)d_in[11];
    const float* blk_br    = (const float*)d_in[12];
    const float* blk_We    = (const float*)d_in[13];
    const float* blk_att   = (const float*)d_in[14];
    // d_in[15] = blk_cb : exactly cancelled by the following BatchNorm
    const float* blk_bng   = (const float*)d_in[16];
    const float* blk_bnb   = (const float*)d_in[17];
    const float* blk_pa    = (const float*)d_in[18];
    const float* post_W1   = (const float*)d_in[19];
    // d_in[20] = post_b1 : cancelled by post BN
    const float* post_g    = (const float*)d_in[21];
    const float* post_beta = (const float*)d_in[22];
    const float* post_a    = (const float*)d_in[23];
    const float* post_W2   = (const float*)d_in[24];
    const float* post_b2   = (const float*)d_in[25];

    const int* srcI = ei;
    const int* dstI = ei + EE;

    float *pRA, *pRB, *pXL, *pXR, *pO, *pRED;
    cudaGetSymbolAddress((void**)&pRA,  g_resA);
    cudaGetSymbolAddress((void**)&pRB,  g_resB);
    cudaGetSymbolAddress((void**)&pXL,  g_xl);
    cudaGetSymbolAddress((void**)&pXR,  g_xr);
    cudaGetSymbolAddress((void**)&pO,   g_o);
    cudaGetSymbolAddress((void**)&pRED, g_red);

    const int GEMM_GRID  = (NN + 63) / 64;
    const int EDGE_GRID  = NN / 16;

    // side stream for the CSR build, overlapped with pre+L0 GEMMs
    cudaStream_t s2;
    cudaStreamCreateWithFlags(&s2, cudaStreamNonBlocking);
    cudaEvent_t evFork, evJoin;
    cudaEventCreateWithFlags(&evFork, cudaEventDisableTiming);
    cudaEventCreateWithFlags(&evJoin, cudaEventDisableTiming);

    cudaEventRecord(evFork, 0);
    cudaStreamWaitEvent(s2, evFork, 0);
    k_zero_csr<<<200, 256, 0, s2>>>();
    k_hist    <<<(EE + 255)/256, 256, 0, s2>>>(dstI);
    k_scan    <<<1, 1024, 0, s2>>>();
    k_scatter <<<(EE + 255)/256, 256, 0, s2>>>(srcI, dstI, eattr);
    cudaEventRecord(evJoin, s2);

    // main stream: BN-slice zero, then pre-GEMM (stats -> red slice 0)
    k_zero_red<<<5, 256>>>();
    k_gemm<<<GEMM_GRID, 256>>>(x, nullptr, nullptr, nullptr, nullptr, nullptr, nullptr,
                               pre_W, pre_b, pre_W, pre_b,
                               pO, nullptr, 0, pRED);

    for (int L = 0; L < 6; L++) {
        const float* Wl = blk_Wl  + L*HH*HH;
        const float* bl = blk_bl  + L*HH;
        const float* Wr = blk_Wr  + L*HH*HH;
        const float* br = blk_br  + L*HH;
        const float* We = blk_We  + L*HH*2;
        const float* at = blk_att + L*HH;

        const float* ared, *agam, *abet, *aa, *ares;
        if (L == 0) {
            ared = pRED; agam = pre_g; abet = pre_beta; aa = pre_a; ares = nullptr;
        } else {
            ared = pRED + L*128;
            agam = blk_bng + (L-1)*HH;
            abet = blk_bnb + (L-1)*HH;
            aa   = blk_pa  + (L-1);
            ares = ((L & 1) == 0) ? ((L == 2) ? pRA : pRB) : nullptr; // prev conv2 residual
        }
        float* hout = ((L & 1) == 0) ? ((L == 0 || L == 4) ? pRA : pRB) : nullptr;

        k_gemm<<<GEMM_GRID, 256>>>(pO, ared, agam, abet, aa, ares, hout,
                                   Wl, bl, Wr, br, pXL, pXR, 1, nullptr);
        if (L == 0) cudaStreamWaitEvent(0, evJoin, 0);   // CSR ready before first edge pass
        k_edge<<<EDGE_GRID, 256>>>(We, at, pRED + (L+1)*128);
    }

    // final apply (block2 conv2) + pooling; residual = resA (written at L=4)
    k_final<<<(NN*16 + 255)/256, 256>>>(pRED + 6*128, blk_bng + 5*HH, blk_bnb + 5*HH,
                                        blk_pa + 5, pRA, batch);

    k_postg1   <<<GG, 256>>>(post_W1);
    k_poststats<<<1, 256>>>(post_g, post_beta);
    k_postg2   <<<GG, 256>>>(post_a, post_W2, post_b2, (float*)d_out);

    cudaEventDestroy(evFork);
    cudaEventDestroy(evJoin);
    cudaStreamDestroy(s2);
}